// round 5
// baseline (speedup 1.0000x reference)
#include <cuda_runtime.h>
#include <cuda_fp16.h>

#define D 64
#define NU_MAX 100001
#define NI_MAX 200001
#define NMAX (NU_MAX + NI_MAX)
#define PMAX 3200000
#define SCAN_BLK 1024

// Scratch (.bss, no allocation).
__device__ __half g_x0[(size_t)NMAX * D];      // quantized layer-0 features
__device__ __half g_h1[(size_t)NMAX * D];      // layer-1 output
__device__ __half g_h2[(size_t)NMAX * D];      // layer-2 output
__device__ int2   g_edge[2 * PMAX];            // packed {col, val_bits}; [0,P)=user CSR, [P,2P)=item CSC
__device__ int    g_u_ptr[NU_MAX + 2];
__device__ int    g_i_ptr[NI_MAX + 2];
__device__ int    g_i_work[NI_MAX + 2];
__device__ int    g_cnt[NI_MAX + 2];
__device__ int    g_bsums[512];

// ---------------------------------------------------------------------------
// init: g_x0 = half(concat(user_emb, item_emb)); zero item counters
// i indexes half2 units (n_total * 32 of them)
// ---------------------------------------------------------------------------
__global__ void init_kernel(const float2* __restrict__ ue,
                            const float2* __restrict__ ie,
                            __half2* __restrict__ x0,
                            int* __restrict__ cnt,
                            int n_user_h2, int n_total_h2, int n_cnt) {
    int i = blockIdx.x * blockDim.x + threadIdx.x;
    if (i < n_cnt) cnt[i] = 0;
    if (i >= n_total_h2) return;
    float2 v = (i < n_user_h2) ? ue[i] : ie[i - n_user_h2];
    x0[i] = __floats2half2_rn(v.x, v.y);
}

// ---------------------------------------------------------------------------
// u_ptr[r] = lower_bound(row[0:P], r)   (first half of row[] is sorted)
// ---------------------------------------------------------------------------
__global__ void build_uptr_kernel(const int* __restrict__ row, int P,
                                  int* __restrict__ uptr, int n_users) {
    int r = blockIdx.x * blockDim.x + threadIdx.x;
    if (r > n_users) return;
    int lo = 0, hi = P;
    while (lo < hi) {
        int mid = (lo + hi) >> 1;
        if (row[mid] < r) lo = mid + 1; else hi = mid;
    }
    uptr[r] = lo;
}

// ---------------------------------------------------------------------------
// count item degrees AND pack the user-block edges {col, val} in one pass
// ---------------------------------------------------------------------------
__global__ void count_pack_kernel(const int* __restrict__ col,
                                  const float* __restrict__ vals, int P,
                                  int* __restrict__ cnt,
                                  int2* __restrict__ edge, int n_users) {
    int e = blockIdx.x * blockDim.x + threadIdx.x;
    if (e >= P) return;
    int c = col[e];
    atomicAdd(&cnt[c - n_users], 1);
    edge[e] = make_int2(c, __float_as_int(vals[e]));
}

// ---------------------------------------------------------------------------
// exclusive scan of cnt[0:n] -> i_ptr (+P offset into packed edge array)
// ---------------------------------------------------------------------------
__global__ void scan1_kernel(const int* __restrict__ cnt, int* __restrict__ ptr,
                             int* __restrict__ bsums, int n) {
    __shared__ int sh[SCAN_BLK];
    int i = blockIdx.x * SCAN_BLK + threadIdx.x;
    int v = (i < n) ? cnt[i] : 0;
    sh[threadIdx.x] = v;
    __syncthreads();
    for (int off = 1; off < SCAN_BLK; off <<= 1) {
        int t = 0;
        if ((int)threadIdx.x >= off) t = sh[threadIdx.x - off];
        __syncthreads();
        sh[threadIdx.x] += t;
        __syncthreads();
    }
    if (i < n) ptr[i] = sh[threadIdx.x] - v;   // exclusive
    if (threadIdx.x == SCAN_BLK - 1) bsums[blockIdx.x] = sh[SCAN_BLK - 1];
}

__global__ void scan2_kernel(int* __restrict__ bsums, int nb) {
    __shared__ int sh[512];
    int v = ((int)threadIdx.x < nb) ? bsums[threadIdx.x] : 0;
    sh[threadIdx.x] = v;
    __syncthreads();
    for (int off = 1; off < 512; off <<= 1) {
        int t = 0;
        if ((int)threadIdx.x >= off) t = sh[threadIdx.x - off];
        __syncthreads();
        sh[threadIdx.x] += t;
        __syncthreads();
    }
    if ((int)threadIdx.x < nb) bsums[threadIdx.x] = sh[threadIdx.x] - v;  // exclusive
}

__global__ void scan3_kernel(int* __restrict__ ptr, int* __restrict__ work,
                             const int* __restrict__ bsums, int n, int offset) {
    int i = blockIdx.x * blockDim.x + threadIdx.x;
    if (i >= n) return;
    int p = ptr[i] + bsums[i >> 10] + offset;
    ptr[i] = p;
    work[i] = p;
}

// ---------------------------------------------------------------------------
// scatter transpose (item CSC) into the packed edge array, single 8B store
// ---------------------------------------------------------------------------
__global__ void scatter_kernel(const int* __restrict__ row,
                               const int* __restrict__ col,
                               const float* __restrict__ vals, int P,
                               int* __restrict__ iwork,
                               int2* __restrict__ edge, int n_users) {
    int e = blockIdx.x * blockDim.x + threadIdx.x;
    if (e >= P) return;
    int it = col[e] - n_users;
    int pos = atomicAdd(&iwork[it], 1);   // already offset by P
    edge[pos] = make_int2(row[e], __float_as_int(vals[e]));
}

// ---------------------------------------------------------------------------
// Warp-per-row SpMM (fp16 gather, fp32 accumulate): y[r] = sum v * x[c]
// lane owns one half2 (4B) of the 128B feature row -> fully coalesced gather.
// Edge data loaded as broadcast int4 pairs (8 edges / unrolled iter).
// ---------------------------------------------------------------------------
#define EDGE_FMA(c_, vbits_)  {                                              \
    float v_ = __int_as_float(vbits_);                                       \
    float2 f_ = __half22float2(x[(size_t)(c_) * 32 + lane]);                 \
    a0 = fmaf(v_, f_.x, a0); a1 = fmaf(v_, f_.y, a1); }

__device__ __forceinline__ void row_accum(const __half2* __restrict__ x,
                                          const int2* __restrict__ edge,
                                          int s, int e, int lane,
                                          float& a0, float& a1) {
    int ei = s;
    if (ei < e && (ei & 1)) {            // align to 16B for int4 loads
        int2 p = edge[ei];
        EDGE_FMA(p.x, p.y)
        ei++;
    }
    for (; ei + 8 <= e; ei += 8) {
        int4 p0 = *reinterpret_cast<const int4*>(edge + ei);
        int4 p1 = *reinterpret_cast<const int4*>(edge + ei + 2);
        int4 p2 = *reinterpret_cast<const int4*>(edge + ei + 4);
        int4 p3 = *reinterpret_cast<const int4*>(edge + ei + 6);
        EDGE_FMA(p0.x, p0.y) EDGE_FMA(p0.z, p0.w)
        EDGE_FMA(p1.x, p1.y) EDGE_FMA(p1.z, p1.w)
        EDGE_FMA(p2.x, p2.y) EDGE_FMA(p2.z, p2.w)
        EDGE_FMA(p3.x, p3.y) EDGE_FMA(p3.z, p3.w)
    }
    for (; ei < e; ei++) {
        int2 p = edge[ei];
        EDGE_FMA(p.x, p.y)
    }
}

__global__ void spmm_kernel(const __half2* __restrict__ x,
                            __half2* __restrict__ y,
                            const int2* __restrict__ edge,
                            const int* __restrict__ uptr,
                            const int* __restrict__ iptr,
                            int n_users, int n_total) {
    int w = (blockIdx.x * blockDim.x + threadIdx.x) >> 5;
    int lane = threadIdx.x & 31;
    if (w >= n_total) return;
    int s, e;
    if (w < n_users) { s = uptr[w]; e = uptr[w + 1]; }
    else { int ii = w - n_users; s = iptr[ii]; e = iptr[ii + 1]; }

    float a0 = 0.f, a1 = 0.f;
    row_accum(x, edge, s, e, lane, a0, a1);
    y[(size_t)w * 32 + lane] = __floats2half2_rn(a0, a1);
}

// last layer fused with the epilogue: out = (x0_f32 + h1 + h2 + acc) * 0.25
__global__ void spmm_final_kernel(const __half2* __restrict__ x,   // h2
                                  const float2* __restrict__ ue,
                                  const float2* __restrict__ ie,
                                  const __half2* __restrict__ h1,
                                  float2* __restrict__ out,
                                  const int2* __restrict__ edge,
                                  const int* __restrict__ uptr,
                                  const int* __restrict__ iptr,
                                  int n_users, int n_total) {
    int w = (blockIdx.x * blockDim.x + threadIdx.x) >> 5;
    int lane = threadIdx.x & 31;
    if (w >= n_total) return;
    int s, e;
    if (w < n_users) { s = uptr[w]; e = uptr[w + 1]; }
    else { int ii = w - n_users; s = iptr[ii]; e = iptr[ii + 1]; }

    float a0 = 0.f, a1 = 0.f;
    row_accum(x, edge, s, e, lane, a0, a1);

    size_t o = (size_t)w * 32 + lane;
    float2 x0 = (w < n_users) ? ue[o] : ie[o - (size_t)n_users * 32];
    float2 f1 = __half22float2(h1[o]);
    float2 f2 = __half22float2(x[o]);
    float2 r;
    r.x = (x0.x + f1.x + f2.x + a0) * 0.25f;
    r.y = (x0.y + f1.y + f2.y + a1) * 0.25f;
    out[o] = r;
}

extern "C" void kernel_launch(void* const* d_in, const int* in_sizes, int n_in,
                              void* d_out, int out_size) {
    const float* user_emb = (const float*)d_in[0];
    const float* item_emb = (const float*)d_in[1];
    const int*   row      = (const int*)d_in[2];
    const int*   col      = (const int*)d_in[3];
    const float* vals     = (const float*)d_in[4];

    const int n_users = in_sizes[0] / D;
    const int n_items = in_sizes[1] / D;
    const int n_total = n_users + n_items;
    const int E       = in_sizes[2];
    const int P       = E / 2;          // first half = user rows (sorted)

    float* out = (float*)d_out;

    __half *x0h, *h1, *h2;
    int *u_ptr, *i_ptr, *i_work, *cnt, *bsums;
    int2 *edge;
    cudaGetSymbolAddress((void**)&x0h, g_x0);
    cudaGetSymbolAddress((void**)&h1, g_h1);
    cudaGetSymbolAddress((void**)&h2, g_h2);
    cudaGetSymbolAddress((void**)&edge, g_edge);
    cudaGetSymbolAddress((void**)&u_ptr, g_u_ptr);
    cudaGetSymbolAddress((void**)&i_ptr, g_i_ptr);
    cudaGetSymbolAddress((void**)&i_work, g_i_work);
    cudaGetSymbolAddress((void**)&cnt, g_cnt);
    cudaGetSymbolAddress((void**)&bsums, g_bsums);

    const int TB = 256;
    const int n_h2 = n_total * (D / 2);       // half2 units
    const int n_user_h2 = n_users * (D / 2);
    const int n_cnt = n_items + 1;

    // 1. init: x0h = half(x0); zero item counters
    init_kernel<<<(n_h2 + TB - 1) / TB, TB>>>(
        (const float2*)user_emb, (const float2*)item_emb,
        (__half2*)x0h, cnt, n_user_h2, n_h2, n_cnt);

    // 2. user CSR pointers (binary search over sorted first half)
    build_uptr_kernel<<<(n_users + 1 + TB - 1) / TB, TB>>>(row, P, u_ptr, n_users);

    // 3. item degrees + pack user-block edges
    count_pack_kernel<<<(P + TB - 1) / TB, TB>>>(col, vals, P, cnt, edge, n_users);

    // 4. exclusive scan -> i_ptr (offset by P into packed edge array)
    int n_scan = n_cnt;
    int nb = (n_scan + SCAN_BLK - 1) / SCAN_BLK;
    scan1_kernel<<<nb, SCAN_BLK>>>(cnt, i_ptr, bsums, n_scan);
    scan2_kernel<<<1, 512>>>(bsums, nb);
    scan3_kernel<<<(n_scan + TB - 1) / TB, TB>>>(i_ptr, i_work, bsums, n_scan, P);

    // 5. scatter transpose (item CSC), packed 8B stores
    scatter_kernel<<<(P + TB - 1) / TB, TB>>>(row, col, vals, P, i_work, edge, n_users);

    // 6. three SpMM layers (warp-per-row, atomic-free, fp16 features)
    int spmm_blocks = (n_total * 32 + TB - 1) / TB;
    spmm_kernel<<<spmm_blocks, TB>>>((const __half2*)x0h, (__half2*)h1,
                                     edge, u_ptr, i_ptr, n_users, n_total);
    spmm_kernel<<<spmm_blocks, TB>>>((const __half2*)h1, (__half2*)h2,
                                     edge, u_ptr, i_ptr, n_users, n_total);
    spmm_final_kernel<<<spmm_blocks, TB>>>((const __half2*)h2,
                                           (const float2*)user_emb, (const float2*)item_emb,
                                           (const __half2*)h1, (float2*)out,
                                           edge, u_ptr, i_ptr, n_users, n_total);
}